// round 2
// baseline (speedup 1.0000x reference)
#include <cuda_runtime.h>

#define CUT0   2000
#define CUT1   20000
#define BATCH  8192
#define HDIM   1024
#define H4     256
#define NCOLS0 18000
#define NCOLS1 30000
#define HEADC  2002

// ---------------- device scratch (no allocations allowed) ----------------
__device__ int   d_idx0[BATCH];
__device__ int   d_idx1[BATCH];
__device__ int   d_counts[2];
__device__ float d_dec0[18432000];  // 18000 x 1024
__device__ float d_dec1[7680000];   // 30000 x 256
__device__ float d_h0[8388608];     // 8192 x 1024
__device__ float d_h1[2097152];     // 8192 x 256

// ---------------- partition targets into cluster index lists -------------
// One block, 1024 threads, 8 targets each. Stable (ascending) order matches
// np.nonzero. Handles BOTH int32 and int64 target buffers: JAX without x64
// silently downcasts jnp.int64 -> int32, so detect layout on-device. For
// int64 (little-endian) the odd 32-bit words are high words == 0 (values
// < 50000); for random int32 targets they are almost surely nonzero.
__global__ void scan_targets_kernel(const int* __restrict__ tw) {
    __shared__ int s0[1024], s1[1024];
    __shared__ int anynz;
    int t = threadIdx.x;
    if (t == 0) anynz = 0;
    __syncthreads();
    int nz = 0;
#pragma unroll
    for (int i = t; i < 4096; i += 1024)
        nz |= (tw[2 * i + 1] != 0);
    if (nz) atomicOr(&anynz, 1);
    __syncthreads();
    int stride = anynz ? 1 : 2;   // int32 : int64

    int v[8];
    int c0 = 0, c1 = 0;
#pragma unroll
    for (int i = 0; i < 8; i++) {
        v[i] = tw[(t * 8 + i) * stride];
        c0 += (v[i] >= CUT0 && v[i] < CUT1) ? 1 : 0;
        c1 += (v[i] >= CUT1) ? 1 : 0;
    }
    s0[t] = c0; s1[t] = c1;
    __syncthreads();
    for (int off = 1; off < 1024; off <<= 1) {
        int a0 = (t >= off) ? s0[t - off] : 0;
        int a1 = (t >= off) ? s1[t - off] : 0;
        __syncthreads();
        s0[t] += a0; s1[t] += a1;
        __syncthreads();
    }
    int p0 = s0[t] - c0, p1 = s1[t] - c1;   // exclusive prefix
#pragma unroll
    for (int i = 0; i < 8; i++) {
        if (v[i] >= CUT0 && v[i] < CUT1)      d_idx0[p0++] = t * 8 + i;
        else if (v[i] >= CUT1)                d_idx1[p1++] = t * 8 + i;
    }
    if (t == 1023) { d_counts[0] = s0[1023]; d_counts[1] = s1[1023]; }
}

// ---------------- generic fp32 GEMM: C = A @ B^T (+bias) -----------------
// A: [M x K] row-major (row stride lda), optional row gather via rowidx.
// B: [N x K] row-major.
// C: row stride ldc, base = Cbase + coff (+ n0*NCOLS0 if add_n0_off).
// M: static (msel==0) or dynamic from d_counts[msel-1].
// Tiles: 128x128 block, BK=8, 256 threads, 8x8 per-thread microtile.
__global__ void __launch_bounds__(256, 2) sgemm_abt_kernel(
    const float* __restrict__ A, const int* __restrict__ rowidx, int lda,
    const float* __restrict__ B, int N, int K,
    float* __restrict__ Cbase, long long coff, int add_n0_off,
    int ldc, const float* __restrict__ bias,
    int Mstatic, int msel)
{
    int M = (msel == 0) ? Mstatic : d_counts[msel - 1];
    int brow0 = blockIdx.y * 128;
    if (brow0 >= M) return;
    int bcol0 = blockIdx.x * 128;

    __shared__ float As[8][128];
    __shared__ float Bs[8][128];

    int tid = threadIdx.x;
    int tx = tid & 15, ty = tid >> 4;

    // load mapping: 256 threads, one float4 of A and one of B each
    int lr  = tid >> 1;          // 0..127 (tile row)
    int lc4 = (tid & 1) * 4;     // 0 or 4 (k offset)

    int arow  = brow0 + lr;
    bool aval = (arow < M);
    int aprow = aval ? (rowidx ? rowidx[arow] : arow) : 0;
    const float* Arow = A + (size_t)aprow * lda + lc4;

    int bcol = bcol0 + lr;
    int bcc  = bcol < N ? bcol : (N - 1);
    const float* Brow = B + (size_t)bcc * K + lc4;

    float acc[8][8];
#pragma unroll
    for (int i = 0; i < 8; i++)
#pragma unroll
        for (int j = 0; j < 8; j++) acc[i][j] = 0.f;

    for (int k0 = 0; k0 < K; k0 += 8) {
        float4 av = aval ? *(const float4*)(Arow + k0)
                         : make_float4(0.f, 0.f, 0.f, 0.f);
        float4 bv = *(const float4*)(Brow + k0);
        As[lc4 + 0][lr] = av.x; As[lc4 + 1][lr] = av.y;
        As[lc4 + 2][lr] = av.z; As[lc4 + 3][lr] = av.w;
        Bs[lc4 + 0][lr] = bv.x; Bs[lc4 + 1][lr] = bv.y;
        Bs[lc4 + 2][lr] = bv.z; Bs[lc4 + 3][lr] = bv.w;
        __syncthreads();
#pragma unroll
        for (int k = 0; k < 8; k++) {
            float4 a0 = *(const float4*)&As[k][ty * 8];
            float4 a1 = *(const float4*)&As[k][ty * 8 + 4];
            float4 b0 = *(const float4*)&Bs[k][tx * 8];
            float4 b1 = *(const float4*)&Bs[k][tx * 8 + 4];
            float a[8] = {a0.x, a0.y, a0.z, a0.w, a1.x, a1.y, a1.z, a1.w};
            float b[8] = {b0.x, b0.y, b0.z, b0.w, b1.x, b1.y, b1.z, b1.w};
#pragma unroll
            for (int i = 0; i < 8; i++)
#pragma unroll
                for (int j = 0; j < 8; j++)
                    acc[i][j] += a[i] * b[j];
        }
        __syncthreads();
    }

    float* C = Cbase + coff +
               (add_n0_off ? (long long)d_counts[0] * (long long)NCOLS0 : 0ll);
#pragma unroll
    for (int i = 0; i < 8; i++) {
        int r = brow0 + ty * 8 + i;
        if (r >= M) continue;
#pragma unroll
        for (int j = 0; j < 8; j++) {
            int c = bcol0 + tx * 8 + j;
            if (c < N)
                C[(size_t)r * ldc + c] = acc[i][j] + (bias ? bias[c] : 0.f);
        }
    }
}

// -------- head tail columns: out[:, 2000:2002] = hidden @ tailW^T + tb ---
__global__ void head_tail_kernel(const float* __restrict__ hidden,
                                 const float* __restrict__ tw,
                                 const float* __restrict__ tb,
                                 float* __restrict__ out) {
    int row  = blockIdx.x * 4 + (threadIdx.x >> 5);
    int lane = threadIdx.x & 31;
    const float* h = hidden + (size_t)row * HDIM;
    float s0 = 0.f, s1 = 0.f;
#pragma unroll
    for (int i = lane; i < HDIM; i += 32) {
        float x = h[i];
        s0 += x * tw[i];
        s1 += x * tw[HDIM + i];
    }
#pragma unroll
    for (int o = 16; o > 0; o >>= 1) {
        s0 += __shfl_xor_sync(0xffffffffu, s0, o);
        s1 += __shfl_xor_sync(0xffffffffu, s1, o);
    }
    if (lane == 0) {
        out[(size_t)row * HEADC + CUT0]     = s0 + tb[0];
        out[(size_t)row * HEADC + CUT0 + 1] = s1 + tb[1];
    }
}

extern "C" void kernel_launch(void* const* d_in, const int* in_sizes, int n_in,
                              void* d_out, int out_size)
{
    (void)in_sizes; (void)n_in; (void)out_size;
    const float* hidden = (const float*)d_in[0];
    const float* embed  = (const float*)d_in[1];
    const float* tailW  = (const float*)d_in[2];
    const float* tailb  = (const float*)d_in[3];
    const float* sbias  = (const float*)d_in[4];
    const float* bias0  = (const float*)d_in[5];
    const float* bias1  = (const float*)d_in[6];
    const float* down0  = (const float*)d_in[7];
    const float* down1  = (const float*)d_in[8];
    const int*   targets = (const int*)d_in[9];
    float* out = (float*)d_out;

    float *p_dec0, *p_dec1, *p_h0, *p_h1;
    int *p_idx0, *p_idx1;
    cudaGetSymbolAddress((void**)&p_dec0, d_dec0);
    cudaGetSymbolAddress((void**)&p_dec1, d_dec1);
    cudaGetSymbolAddress((void**)&p_h0,   d_h0);
    cudaGetSymbolAddress((void**)&p_h1,   d_h1);
    cudaGetSymbolAddress((void**)&p_idx0, d_idx0);
    cudaGetSymbolAddress((void**)&p_idx1, d_idx1);

    dim3 blk(256);

    // 1. partition targets -> idx0/idx1 + counts (dtype-agnostic)
    scan_targets_kernel<<<1, 1024>>>(targets);

    // 2. head shortlist: [8192 x 2000] = hidden @ embed[:2000]^T + sbias
    sgemm_abt_kernel<<<dim3(16, 64), blk>>>(hidden, nullptr, HDIM,
                                            embed, CUT0, HDIM,
                                            out, 0, 0, HEADC, sbias,
                                            BATCH, 0);
    // 3. head tail columns
    head_tail_kernel<<<BATCH / 4, 128>>>(hidden, tailW, tailb, out);

    // 4. dec0 [18000 x 1024] = embed[2000:20000] @ down0^T
    sgemm_abt_kernel<<<dim3(8, 141), blk>>>(embed + (size_t)CUT0 * HDIM, nullptr, HDIM,
                                            down0, HDIM, HDIM,
                                            p_dec0, 0, 0, HDIM, nullptr,
                                            NCOLS0, 0);
    // 5. dec1 [30000 x 256] = embed[20000:50000] @ down1^T
    sgemm_abt_kernel<<<dim3(2, 235), blk>>>(embed + (size_t)CUT1 * HDIM, nullptr, HDIM,
                                            down1, H4, HDIM,
                                            p_dec1, 0, 0, H4, nullptr,
                                            NCOLS1, 0);
    // 6. h0 [n0 x 1024] = hidden[idx0] @ down0^T   (gathered A)
    sgemm_abt_kernel<<<dim3(8, 64), blk>>>(hidden, p_idx0, HDIM,
                                           down0, HDIM, HDIM,
                                           p_h0, 0, 0, HDIM, nullptr,
                                           0, 1);
    // 7. out0 [n0 x 18000] = h0 @ dec0^T + bias0
    sgemm_abt_kernel<<<dim3(141, 64), blk>>>(p_h0, nullptr, HDIM,
                                             p_dec0, NCOLS0, HDIM,
                                             out, (long long)BATCH * HEADC, 0,
                                             NCOLS0, bias0, 0, 1);
    // 8. h1 [n1 x 256] = hidden[idx1] @ down1^T   (gathered A)
    sgemm_abt_kernel<<<dim3(2, 64), blk>>>(hidden, p_idx1, HDIM,
                                           down1, H4, HDIM,
                                           p_h1, 0, 0, H4, nullptr,
                                           0, 2);
    // 9. out1 [n1 x 30000] = h1 @ dec1^T + bias1 (offset depends on n0)
    sgemm_abt_kernel<<<dim3(235, 64), blk>>>(p_h1, nullptr, H4,
                                             p_dec1, NCOLS1, H4,
                                             out, (long long)BATCH * HEADC, 1,
                                             NCOLS1, bias1, 0, 2);
}